// round 8
// baseline (speedup 1.0000x reference)
#include <cuda_runtime.h>
#include <cstdint>

#define P_NUM 65536
#define B_NUM 8
#define G_NUM 64
#define NBX 16
#define NBY 16
#define NBINS 1024                        // 4 size classes x 256 center bins
#define P_BITS 17
#define P_MASK 0x1FFFFu
#define TOTAL_MATCH_BLOCKS (128 * 8)
#define FP_INVALID 0x10000u               // sentinel > any real p (p < 65536)
#define ENC_MIN(bits) (0x7F800000 - (bits))   // zero-init == +inf identity

// ---------------- persistent device scratch (.bss zero == reset state) ----
__device__ unsigned int       d_bin_count[NBINS];     // reset by k_match last block
__device__ int                d_bb_enc[4][NBINS];     // reset by k_match last block
__device__ unsigned int       d_bin_off[NBINS];
__device__ unsigned int       d_binrank[P_NUM];       // bin<<17 | rank
__device__ unsigned int       d_perm[P_NUM];          // bin<<17 | p
__device__ unsigned long long d_cand_mask[B_NUM * NBINS];
__device__ unsigned long long g_best[B_NUM * G_NUM];  // reset by k_match last block
__device__ unsigned int       d_ticket1;              // k_bin, self-resetting
__device__ unsigned int       d_ticket2;              // k_match, self-resetting

// ---------------- phase A: bin priors + inline scan by last block ---------
__global__ __launch_bounds__(512)
void k_bin(const float4* __restrict__ priors)
{
    __shared__ unsigned int s_cnt[NBINS];
    __shared__ int          s_bb[4][NBINS];
    __shared__ unsigned int s_base[NBINS];
    __shared__ unsigned int s_scan[512];
    __shared__ int          s_last;
    const int tid = threadIdx.x;
#pragma unroll
    for (int i = tid; i < NBINS; i += 512) {
        s_cnt[i] = 0;
        s_bb[0][i] = 0; s_bb[1][i] = 0; s_bb[2][i] = 0; s_bb[3][i] = 0;
    }
    __syncthreads();

    const int p = blockIdx.x * 512 + tid;
    float4 pr = priors[p];
    float cx = (pr.x + pr.z) * 0.5f;
    float cy = (pr.y + pr.w) * 0.5f;
    int bx = (int)((cx - 0.1f) * (NBX / 0.8f));
    int by = (int)((cy - 0.1f) * (NBY / 0.8f));
    bx = bx < 0 ? 0 : (bx > NBX - 1 ? NBX - 1 : bx);
    by = by < 0 ? 0 : (by > NBY - 1 ? NBY - 1 : by);
    int cls = ((pr.z - pr.x) >= 0.12f ? 1 : 0) | ((pr.w - pr.y) >= 0.12f ? 2 : 0);
    const int bin = (cls << 8) | (by * NBX + bx);
    unsigned int lrank = atomicAdd(&s_cnt[bin], 1u);
    atomicMax(&s_bb[0][bin], ENC_MIN(__float_as_int(pr.x)));
    atomicMax(&s_bb[1][bin], ENC_MIN(__float_as_int(pr.y)));
    atomicMax(&s_bb[2][bin], __float_as_int(pr.z));
    atomicMax(&s_bb[3][bin], __float_as_int(pr.w));
    __syncthreads();

#pragma unroll
    for (int i = tid; i < NBINS; i += 512) {
        if (s_cnt[i] > 0) {
            s_base[i] = atomicAdd(&d_bin_count[i], s_cnt[i]);
            atomicMax(&d_bb_enc[0][i], s_bb[0][i]);
            atomicMax(&d_bb_enc[1][i], s_bb[1][i]);
            atomicMax(&d_bb_enc[2][i], s_bb[2][i]);
            atomicMax(&d_bb_enc[3][i], s_bb[3][i]);
        }
    }
    __syncthreads();

    d_binrank[p] = ((unsigned int)bin << P_BITS) | (s_base[bin] + lrank);

    __threadfence();
    if (tid == 0) {
        unsigned int t = atomicAdd(&d_ticket1, 1u);
        s_last = (t == gridDim.x - 1);
    }
    __syncthreads();
    if (s_last) {
        unsigned int c0 = d_bin_count[2 * tid];
        unsigned int c1 = d_bin_count[2 * tid + 1];
        s_scan[tid] = c0 + c1;
        __syncthreads();
        for (int d = 1; d < 512; d <<= 1) {
            unsigned int v = (tid >= d) ? s_scan[tid - d] : 0u;
            __syncthreads();
            s_scan[tid] += v;
            __syncthreads();
        }
        unsigned int excl = s_scan[tid] - c0 - c1;
        d_bin_off[2 * tid]     = excl;
        d_bin_off[2 * tid + 1] = excl + c0;
        if (tid == 0) d_ticket1 = 0;          // self-reset for next call
    }
}

// ---------------- phase B: blocks 0..15 = GT masks, rest = scatter --------
__global__ __launch_bounds__(512)
void k_prep(const float4* __restrict__ gt_boxes)
{
    const int tid = threadIdx.x;
    if (blockIdx.x < 16) {
        __shared__ float4 sg[G_NUM];
        const int pair = blockIdx.x * 512 + tid;   // [0, 8192)
        const int b    = pair >> 10;               // uniform within block
        const int bin  = pair & (NBINS - 1);
        if (tid < G_NUM) sg[tid] = gt_boxes[b * G_NUM + tid];
        __syncthreads();
        float minx0 = __int_as_float(ENC_MIN(d_bb_enc[0][bin]));
        float miny0 = __int_as_float(ENC_MIN(d_bb_enc[1][bin]));
        float maxx1 = __int_as_float(d_bb_enc[2][bin]);
        float maxy1 = __int_as_float(d_bb_enc[3][bin]);
        unsigned long long mask = 0ull;
        for (int g = 0; g < G_NUM; g++) {
            float4 gb = sg[g];
            // exact conservative reject: skipped pairs have intersection == 0
            bool keep = (gb.z > minx0) & (gb.x < maxx1) &
                        (gb.w > miny0) & (gb.y < maxy1);
            if (keep) mask |= 1ull << g;
        }
        d_cand_mask[pair] = mask;
    } else {
        const int p = (blockIdx.x - 16) * 512 + tid;
        unsigned int br   = d_binrank[p];
        unsigned int bin  = br >> P_BITS;
        unsigned int slot = d_bin_off[bin] + (br & P_MASK);
        d_perm[slot] = (bin << P_BITS) | (unsigned int)p;
    }
}

// ---------------- phase C: main matching (+ fused fixup in last block) ----
__global__ __launch_bounds__(256)
void k_match(const float4* __restrict__ priors,
             const float4* __restrict__ gt_boxes,
             const int*    __restrict__ gt_labels,
             float* __restrict__ out_loc,
             float* __restrict__ out_conf)
{
    __shared__ float4 s_box[G_NUM];
    __shared__ float  s_area[G_NUM];
    __shared__ int    s_lab[G_NUM];
    __shared__ unsigned long long s_best[G_NUM];
    __shared__ unsigned int s_fp[B_NUM * G_NUM];
    __shared__ int s_last;

    const int b   = blockIdx.y;
    const int tid = threadIdx.x;

    if (tid < G_NUM) {
        float4 g4 = gt_boxes[b * G_NUM + tid];
        s_box[tid]  = g4;
        s_area[tid] = (g4.z - g4.x) * (g4.w - g4.y);
        s_lab[tid]  = gt_labels[b * G_NUM + tid];
        s_best[tid] = 0ull;
    }
    __syncthreads();

    // two slots per thread
    const unsigned int e0 = d_perm[blockIdx.x * 512 + tid];
    const unsigned int e1 = d_perm[blockIdx.x * 512 + 256 + tid];
    const unsigned int p0 = e0 & P_MASK,  bin0 = e0 >> P_BITS;
    const unsigned int p1 = e1 & P_MASK,  bin1 = e1 >> P_BITS;

    // exact union of all lanes' bin masks (conservative: extras have IoU==0)
    unsigned long long mm = d_cand_mask[(b << 10) | bin0]
                          | d_cand_mask[(b << 10) | bin1];
    unsigned int mlo = __reduce_or_sync(0xffffffffu, (unsigned int)mm);
    unsigned int mhi = __reduce_or_sync(0xffffffffu, (unsigned int)(mm >> 32));
    unsigned long long m = ((unsigned long long)mhi << 32) | mlo;

    const float4 pr0 = priors[p0];
    const float4 pr1 = priors[p1];
    const float  pa0 = (pr0.z - pr0.x) * (pr0.w - pr0.y);
    const float  pa1 = (pr1.z - pr1.x) * (pr1.w - pr1.y);

    float bi0 = 0.0f, bi1 = 0.0f;   // all-zero column -> g=0 (jnp.argmax)
    int   bg0 = 0,    bg1 = 0;

    while (m) {
        const int g = __ffsll((long long)m) - 1;    // ascending g
        m &= m - 1;
        const float4 gb = s_box[g];
        const float  ga = s_area[g];
        // prior 0 — exact reference op order
        float ltx0 = fmaxf(pr0.x, gb.x), lty0 = fmaxf(pr0.y, gb.y);
        float rbx0 = fminf(pr0.z, gb.z), rby0 = fminf(pr0.w, gb.w);
        float wx0 = fmaxf(rbx0 - ltx0, 0.0f), wy0 = fmaxf(rby0 - lty0, 0.0f);
        float in0 = wx0 * wy0;
        float iou0 = in0 / ((pa0 + ga) - in0);
        // prior 1
        float ltx1 = fmaxf(pr1.x, gb.x), lty1 = fmaxf(pr1.y, gb.y);
        float rbx1 = fminf(pr1.z, gb.z), rby1 = fminf(pr1.w, gb.w);
        float wx1 = fmaxf(rbx1 - ltx1, 0.0f), wy1 = fmaxf(rby1 - lty1, 0.0f);
        float in1 = wx1 * wy1;
        float iou1 = in1 / ((pa1 + ga) - in1);

        if (iou0 > bi0) { bi0 = iou0; bg0 = g; }    // first max wins
        if (iou1 > bi1) { bi1 = iou1; bg1 = g; }

        // thread-local candidate, then warp max; ~p in atomic key picks
        // smallest p on ties (first-occurrence, like jnp.argmax)
        unsigned int u0 = __float_as_uint(iou0);    // iou >= 0: monotone bits
        unsigned int u1 = __float_as_uint(iou1);
        unsigned int uc, pc;
        if (u1 > u0 || (u1 == u0 && p1 < p0)) { uc = u1; pc = p1; }
        else                                  { uc = u0; pc = p0; }
        unsigned int wb = __reduce_max_sync(0xffffffffu, uc);
        if (uc == wb && wb != 0u) {
            unsigned long long key =
                ((unsigned long long)wb << 32) | (unsigned long long)(~pc);
            atomicMax(&s_best[g], key);
        }
    }

    // epilogue: encode + conf for both slots
    {
        const float4 mb = s_box[bg0];
        const int    cv = (bi0 < 0.5f) ? 0 : (s_lab[bg0] + 1);
        float pw = pr0.z - pr0.x, ph = pr0.w - pr0.y;
        float4 loc;
        loc.x = (((mb.x + mb.z) * 0.5f) - ((pr0.x + pr0.z) * 0.5f)) / (0.1f * pw);
        loc.y = (((mb.y + mb.w) * 0.5f) - ((pr0.y + pr0.w) * 0.5f)) / (0.1f * ph);
        loc.z = logf((mb.z - mb.x) / pw) / 0.2f;
        loc.w = logf((mb.w - mb.y) / ph) / 0.2f;
        reinterpret_cast<float4*>(out_loc)[(size_t)b * P_NUM + p0] = loc;
        if (out_conf) out_conf[(size_t)b * P_NUM + p0] = (float)cv;
    }
    {
        const float4 mb = s_box[bg1];
        const int    cv = (bi1 < 0.5f) ? 0 : (s_lab[bg1] + 1);
        float pw = pr1.z - pr1.x, ph = pr1.w - pr1.y;
        float4 loc;
        loc.x = (((mb.x + mb.z) * 0.5f) - ((pr1.x + pr1.z) * 0.5f)) / (0.1f * pw);
        loc.y = (((mb.y + mb.w) * 0.5f) - ((pr1.y + pr1.w) * 0.5f)) / (0.1f * ph);
        loc.z = logf((mb.z - mb.x) / pw) / 0.2f;
        loc.w = logf((mb.w - mb.y) / ph) / 0.2f;
        reinterpret_cast<float4*>(out_loc)[(size_t)b * P_NUM + p1] = loc;
        if (out_conf) out_conf[(size_t)b * P_NUM + p1] = (float)cv;
    }

    __syncthreads();
    if (tid < G_NUM) {
        unsigned long long v = s_best[tid];
        if (v) atomicMax(&g_best[(b << 6) + tid], v);
    }

    // ---- last-block ticket: fused forced-prior fixup + scratch resets ----
    __threadfence();
    if (tid == 0) {
        unsigned int t = atomicAdd(&d_ticket2, 1u);
        s_last = (t == TOTAL_MATCH_BLOCKS - 1);
    }
    __syncthreads();
    if (!s_last) return;
    __threadfence();

    // gather winners, reset g_best
    for (int i = tid; i < B_NUM * G_NUM; i += 256) {
        unsigned long long key = g_best[i];
        g_best[i] = 0ull;
        s_fp[i] = key ? ~((unsigned int)(key & 0xFFFFFFFFull)) : FP_INVALID;
    }
    __syncthreads();

    // replicate scatter semantics: for duplicate priors, the LAST g wins
    for (int i = tid; i < B_NUM * G_NUM; i += 256) {
        const unsigned int p = s_fp[i];
        if (p == FP_INVALID) continue;           // GT overlapped nothing
        const int bb = i >> 6;
        const int g  = i & 63;
        bool dup = false;
        for (int g2 = g + 1; g2 < G_NUM; g2++)
            if (s_fp[(bb << 6) + g2] == p) { dup = true; break; }
        if (dup) continue;

        const float4 mg = gt_boxes[bb * G_NUM + g];
        const float4 pb = priors[p];
        float pw = pb.z - pb.x, ph = pb.w - pb.y;
        float4 loc;
        loc.x = (((mg.x + mg.z) * 0.5f) - ((pb.x + pb.z) * 0.5f)) / (0.1f * pw);
        loc.y = (((mg.y + mg.w) * 0.5f) - ((pb.y + pb.w) * 0.5f)) / (0.1f * ph);
        loc.z = logf((mg.z - mg.x) / pw) / 0.2f;
        loc.w = logf((mg.w - mg.y) / ph) / 0.2f;
        reinterpret_cast<float4*>(out_loc)[(size_t)bb * P_NUM + p] = loc;
        if (out_conf)
            out_conf[(size_t)bb * P_NUM + p] = (float)(gt_labels[bb * G_NUM + g] + 1);
    }

    // reset bin scratch for the next call
    for (int i = tid; i < NBINS; i += 256) {
        d_bin_count[i] = 0;
        d_bb_enc[0][i] = 0; d_bb_enc[1][i] = 0;
        d_bb_enc[2][i] = 0; d_bb_enc[3][i] = 0;
    }
    if (tid == 0) d_ticket2 = 0;                 // self-reset for next call
}

extern "C" void kernel_launch(void* const* d_in, const int* in_sizes, int n_in,
                              void* d_out, int out_size)
{
    const float4* priors    = (const float4*)d_in[0];   // [P,4] f32
    const float4* gt_boxes  = (const float4*)d_in[1];   // [B,G,4] f32
    const int*    gt_labels = (const int*)d_in[2];      // [B,G] i32

    float* out = (float*)d_out;
    float* out_loc  = out;                                           // [B,P,4]
    float* out_conf = (out_size >= B_NUM * P_NUM * 5)
                        ? out + (size_t)B_NUM * P_NUM * 4 : nullptr; // [B,P]

    k_bin  <<<P_NUM / 512, 512>>>(priors);
    k_prep <<<16 + P_NUM / 512, 512>>>(gt_boxes);
    dim3 grid(P_NUM / 512, B_NUM);                                   // (128, 8)
    k_match<<<grid, 256>>>(priors, gt_boxes, gt_labels, out_loc, out_conf);
}

// round 9
// speedup vs baseline: 1.0923x; 1.0923x over previous
#include <cuda_runtime.h>
#include <cstdint>

#define P_NUM 65536
#define B_NUM 8
#define G_NUM 64
#define NBX 16
#define NBY 16
#define NBINS 1024                        // 4 size classes x 256 center bins
#define P_BITS 17
#define P_MASK 0x1FFFFu
#define TOTAL_MATCH_BLOCKS (128 * 8)
#define FP_INVALID 0x10000u               // sentinel > any real p (p < 65536)
#define ENC_MIN(bits) (0x7F800000 - (bits))   // zero-init == +inf identity

// ---------------- persistent device scratch (.bss zero == reset state) ----
__device__ unsigned int       d_bin_count[NBINS];     // reset by k_match last block
__device__ int                d_bb_enc[4][NBINS];     // reset by k_match last block
__device__ unsigned int       d_bin_off[NBINS];
__device__ unsigned int       d_binrank[P_NUM];       // bin<<17 | rank
__device__ unsigned int       d_perm[P_NUM];          // bin<<17 | p
__device__ unsigned long long d_cand_mask[B_NUM * NBINS];
__device__ unsigned long long g_best[B_NUM * G_NUM];  // reset by k_match last block
__device__ unsigned int       d_ticket1;              // k_bin, self-resetting
__device__ unsigned int       d_ticket2;              // k_match, self-resetting

// ---------------- phase A: bin priors + inline scan by last block ---------
__global__ __launch_bounds__(512)
void k_bin(const float4* __restrict__ priors)
{
    __shared__ unsigned int s_cnt[NBINS];
    __shared__ int          s_bb[4][NBINS];
    __shared__ unsigned int s_base[NBINS];
    __shared__ unsigned int s_scan[512];
    __shared__ int          s_last;
    const int tid = threadIdx.x;
#pragma unroll
    for (int i = tid; i < NBINS; i += 512) {
        s_cnt[i] = 0;
        s_bb[0][i] = 0; s_bb[1][i] = 0; s_bb[2][i] = 0; s_bb[3][i] = 0;
    }
    __syncthreads();

    const int p = blockIdx.x * 512 + tid;
    float4 pr = priors[p];
    float cx = (pr.x + pr.z) * 0.5f;
    float cy = (pr.y + pr.w) * 0.5f;
    int bx = (int)((cx - 0.1f) * (NBX / 0.8f));
    int by = (int)((cy - 0.1f) * (NBY / 0.8f));
    bx = bx < 0 ? 0 : (bx > NBX - 1 ? NBX - 1 : bx);
    by = by < 0 ? 0 : (by > NBY - 1 ? NBY - 1 : by);
    int cls = ((pr.z - pr.x) >= 0.12f ? 1 : 0) | ((pr.w - pr.y) >= 0.12f ? 2 : 0);
    const int bin = (cls << 8) | (by * NBX + bx);
    unsigned int lrank = atomicAdd(&s_cnt[bin], 1u);
    atomicMax(&s_bb[0][bin], ENC_MIN(__float_as_int(pr.x)));
    atomicMax(&s_bb[1][bin], ENC_MIN(__float_as_int(pr.y)));
    atomicMax(&s_bb[2][bin], __float_as_int(pr.z));
    atomicMax(&s_bb[3][bin], __float_as_int(pr.w));
    __syncthreads();

#pragma unroll
    for (int i = tid; i < NBINS; i += 512) {
        if (s_cnt[i] > 0) {
            s_base[i] = atomicAdd(&d_bin_count[i], s_cnt[i]);
            atomicMax(&d_bb_enc[0][i], s_bb[0][i]);
            atomicMax(&d_bb_enc[1][i], s_bb[1][i]);
            atomicMax(&d_bb_enc[2][i], s_bb[2][i]);
            atomicMax(&d_bb_enc[3][i], s_bb[3][i]);
        }
    }
    __syncthreads();

    d_binrank[p] = ((unsigned int)bin << P_BITS) | (s_base[bin] + lrank);

    __threadfence();
    if (tid == 0) {
        unsigned int t = atomicAdd(&d_ticket1, 1u);
        s_last = (t == gridDim.x - 1);
    }
    __syncthreads();
    if (s_last) {
        unsigned int c0 = d_bin_count[2 * tid];
        unsigned int c1 = d_bin_count[2 * tid + 1];
        s_scan[tid] = c0 + c1;
        __syncthreads();
        for (int d = 1; d < 512; d <<= 1) {
            unsigned int v = (tid >= d) ? s_scan[tid - d] : 0u;
            __syncthreads();
            s_scan[tid] += v;
            __syncthreads();
        }
        unsigned int excl = s_scan[tid] - c0 - c1;
        d_bin_off[2 * tid]     = excl;
        d_bin_off[2 * tid + 1] = excl + c0;
        if (tid == 0) d_ticket1 = 0;          // self-reset for next call
    }
}

// ---------------- phase B: blocks 0..15 = GT masks, rest = scatter --------
__global__ __launch_bounds__(512)
void k_prep(const float4* __restrict__ gt_boxes)
{
    const int tid = threadIdx.x;
    if (blockIdx.x < 16) {
        __shared__ float4 sg[G_NUM];
        const int pair = blockIdx.x * 512 + tid;   // [0, 8192)
        const int b    = pair >> 10;               // uniform within block
        const int bin  = pair & (NBINS - 1);
        if (tid < G_NUM) sg[tid] = gt_boxes[b * G_NUM + tid];
        __syncthreads();
        float minx0 = __int_as_float(ENC_MIN(d_bb_enc[0][bin]));
        float miny0 = __int_as_float(ENC_MIN(d_bb_enc[1][bin]));
        float maxx1 = __int_as_float(d_bb_enc[2][bin]);
        float maxy1 = __int_as_float(d_bb_enc[3][bin]);
        unsigned long long mask = 0ull;
        for (int g = 0; g < G_NUM; g++) {
            float4 gb = sg[g];
            // exact conservative reject: skipped pairs have intersection == 0
            bool keep = (gb.z > minx0) & (gb.x < maxx1) &
                        (gb.w > miny0) & (gb.y < maxy1);
            if (keep) mask |= 1ull << g;
        }
        d_cand_mask[pair] = mask;
    } else {
        const int p = (blockIdx.x - 16) * 512 + tid;
        unsigned int br   = d_binrank[p];
        unsigned int bin  = br >> P_BITS;
        unsigned int slot = d_bin_off[bin] + (br & P_MASK);
        d_perm[slot] = (bin << P_BITS) | (unsigned int)p;
    }
}

// ---------------- phase C: main matching (+ fused fixup in last block) ----
__global__ __launch_bounds__(256)
void k_match(const float4* __restrict__ priors,
             const float4* __restrict__ gt_boxes,
             const int*    __restrict__ gt_labels,
             float* __restrict__ out_loc,
             float* __restrict__ out_conf)
{
    __shared__ float4 s_box[G_NUM];
    __shared__ float  s_area[G_NUM];
    __shared__ int    s_lab[G_NUM];
    __shared__ unsigned long long s_best[G_NUM];
    __shared__ unsigned int s_fp[B_NUM * G_NUM];
    __shared__ int s_last;

    const int b   = blockIdx.y;
    const int tid = threadIdx.x;

    if (tid < G_NUM) {
        float4 g4 = gt_boxes[b * G_NUM + tid];
        s_box[tid]  = g4;
        s_area[tid] = (g4.z - g4.x) * (g4.w - g4.y);
        s_lab[tid]  = gt_labels[b * G_NUM + tid];
        s_best[tid] = 0ull;
    }
    __syncthreads();

    // two ADJACENT slots per thread (same bin almost always -> coherent masks)
    const unsigned int sbase = blockIdx.x * 512 + 2 * tid;
    const unsigned int e0 = d_perm[sbase];
    const unsigned int e1 = d_perm[sbase + 1];
    const unsigned int p0 = e0 & P_MASK,  bin0 = e0 >> P_BITS;
    const unsigned int p1 = e1 & P_MASK,  bin1 = e1 >> P_BITS;

    // exact union of all lanes' bin masks (conservative: extras have IoU==0)
    unsigned long long mm = d_cand_mask[(b << 10) | bin0]
                          | d_cand_mask[(b << 10) | bin1];
    unsigned int mlo = __reduce_or_sync(0xffffffffu, (unsigned int)mm);
    unsigned int mhi = __reduce_or_sync(0xffffffffu, (unsigned int)(mm >> 32));
    unsigned long long m = ((unsigned long long)mhi << 32) | mlo;

    const float4 pr0 = priors[p0];
    const float4 pr1 = priors[p1];
    const float  pa0 = (pr0.z - pr0.x) * (pr0.w - pr0.y);
    const float  pa1 = (pr1.z - pr1.x) * (pr1.w - pr1.y);

    float bi0 = 0.0f, bi1 = 0.0f;   // all-zero column -> g=0 (jnp.argmax)
    int   bg0 = 0,    bg1 = 0;

    while (m) {
        const int g = __ffsll((long long)m) - 1;    // ascending g
        m &= m - 1;
        const float4 gb = s_box[g];
        const float  ga = s_area[g];
        // prior 0 — exact reference op order
        float ltx0 = fmaxf(pr0.x, gb.x), lty0 = fmaxf(pr0.y, gb.y);
        float rbx0 = fminf(pr0.z, gb.z), rby0 = fminf(pr0.w, gb.w);
        float wx0 = fmaxf(rbx0 - ltx0, 0.0f), wy0 = fmaxf(rby0 - lty0, 0.0f);
        float in0 = wx0 * wy0;
        float iou0 = in0 / ((pa0 + ga) - in0);
        // prior 1
        float ltx1 = fmaxf(pr1.x, gb.x), lty1 = fmaxf(pr1.y, gb.y);
        float rbx1 = fminf(pr1.z, gb.z), rby1 = fminf(pr1.w, gb.w);
        float wx1 = fmaxf(rbx1 - ltx1, 0.0f), wy1 = fmaxf(rby1 - lty1, 0.0f);
        float in1 = wx1 * wy1;
        float iou1 = in1 / ((pa1 + ga) - in1);

        if (iou0 > bi0) { bi0 = iou0; bg0 = g; }    // first max wins
        if (iou1 > bi1) { bi1 = iou1; bg1 = g; }

        // thread-local candidate, then warp max; ~p in atomic key picks
        // smallest p on ties (first-occurrence, like jnp.argmax)
        unsigned int u0 = __float_as_uint(iou0);    // iou >= 0: monotone bits
        unsigned int u1 = __float_as_uint(iou1);
        unsigned int uc, pc;
        if (u1 > u0 || (u1 == u0 && p1 < p0)) { uc = u1; pc = p1; }
        else                                  { uc = u0; pc = p0; }
        unsigned int wb = __reduce_max_sync(0xffffffffu, uc);
        if (uc == wb && wb != 0u) {
            unsigned long long key =
                ((unsigned long long)wb << 32) | (unsigned long long)(~pc);
            atomicMax(&s_best[g], key);
        }
    }

    // epilogue: encode + conf for both slots
    {
        const float4 mb = s_box[bg0];
        const int    cv = (bi0 < 0.5f) ? 0 : (s_lab[bg0] + 1);
        float pw = pr0.z - pr0.x, ph = pr0.w - pr0.y;
        float4 loc;
        loc.x = (((mb.x + mb.z) * 0.5f) - ((pr0.x + pr0.z) * 0.5f)) / (0.1f * pw);
        loc.y = (((mb.y + mb.w) * 0.5f) - ((pr0.y + pr0.w) * 0.5f)) / (0.1f * ph);
        loc.z = logf((mb.z - mb.x) / pw) / 0.2f;
        loc.w = logf((mb.w - mb.y) / ph) / 0.2f;
        reinterpret_cast<float4*>(out_loc)[(size_t)b * P_NUM + p0] = loc;
        if (out_conf) out_conf[(size_t)b * P_NUM + p0] = (float)cv;
    }
    {
        const float4 mb = s_box[bg1];
        const int    cv = (bi1 < 0.5f) ? 0 : (s_lab[bg1] + 1);
        float pw = pr1.z - pr1.x, ph = pr1.w - pr1.y;
        float4 loc;
        loc.x = (((mb.x + mb.z) * 0.5f) - ((pr1.x + pr1.z) * 0.5f)) / (0.1f * pw);
        loc.y = (((mb.y + mb.w) * 0.5f) - ((pr1.y + pr1.w) * 0.5f)) / (0.1f * ph);
        loc.z = logf((mb.z - mb.x) / pw) / 0.2f;
        loc.w = logf((mb.w - mb.y) / ph) / 0.2f;
        reinterpret_cast<float4*>(out_loc)[(size_t)b * P_NUM + p1] = loc;
        if (out_conf) out_conf[(size_t)b * P_NUM + p1] = (float)cv;
    }

    __syncthreads();
    if (tid < G_NUM) {
        unsigned long long v = s_best[tid];
        if (v) atomicMax(&g_best[(b << 6) + tid], v);
    }

    // ---- last-block ticket: fused forced-prior fixup + scratch resets ----
    __threadfence();
    if (tid == 0) {
        unsigned int t = atomicAdd(&d_ticket2, 1u);
        s_last = (t == TOTAL_MATCH_BLOCKS - 1);
    }
    __syncthreads();
    if (!s_last) return;
    __threadfence();

    // gather winners, reset g_best
    for (int i = tid; i < B_NUM * G_NUM; i += 256) {
        unsigned long long key = g_best[i];
        g_best[i] = 0ull;
        s_fp[i] = key ? ~((unsigned int)(key & 0xFFFFFFFFull)) : FP_INVALID;
    }
    __syncthreads();

    // replicate scatter semantics: for duplicate priors, the LAST g wins
    for (int i = tid; i < B_NUM * G_NUM; i += 256) {
        const unsigned int p = s_fp[i];
        if (p == FP_INVALID) continue;           // GT overlapped nothing
        const int bb = i >> 6;
        const int g  = i & 63;
        bool dup = false;
        for (int g2 = g + 1; g2 < G_NUM; g2++)
            if (s_fp[(bb << 6) + g2] == p) { dup = true; break; }
        if (dup) continue;

        const float4 mg = gt_boxes[bb * G_NUM + g];
        const float4 pb = priors[p];
        float pw = pb.z - pb.x, ph = pb.w - pb.y;
        float4 loc;
        loc.x = (((mg.x + mg.z) * 0.5f) - ((pb.x + pb.z) * 0.5f)) / (0.1f * pw);
        loc.y = (((mg.y + mg.w) * 0.5f) - ((pb.y + pb.w) * 0.5f)) / (0.1f * ph);
        loc.z = logf((mg.z - mg.x) / pw) / 0.2f;
        loc.w = logf((mg.w - mg.y) / ph) / 0.2f;
        reinterpret_cast<float4*>(out_loc)[(size_t)bb * P_NUM + p] = loc;
        if (out_conf)
            out_conf[(size_t)bb * P_NUM + p] = (float)(gt_labels[bb * G_NUM + g] + 1);
    }

    // reset bin scratch for the next call
    for (int i = tid; i < NBINS; i += 256) {
        d_bin_count[i] = 0;
        d_bb_enc[0][i] = 0; d_bb_enc[1][i] = 0;
        d_bb_enc[2][i] = 0; d_bb_enc[3][i] = 0;
    }
    if (tid == 0) d_ticket2 = 0;                 // self-reset for next call
}

extern "C" void kernel_launch(void* const* d_in, const int* in_sizes, int n_in,
                              void* d_out, int out_size)
{
    const float4* priors    = (const float4*)d_in[0];   // [P,4] f32
    const float4* gt_boxes  = (const float4*)d_in[1];   // [B,G,4] f32
    const int*    gt_labels = (const int*)d_in[2];      // [B,G] i32

    float* out = (float*)d_out;
    float* out_loc  = out;                                           // [B,P,4]
    float* out_conf = (out_size >= B_NUM * P_NUM * 5)
                        ? out + (size_t)B_NUM * P_NUM * 4 : nullptr; // [B,P]

    k_bin  <<<P_NUM / 512, 512>>>(priors);
    k_prep <<<16 + P_NUM / 512, 512>>>(gt_boxes);
    dim3 grid(P_NUM / 512, B_NUM);                                   // (128, 8)
    k_match<<<grid, 256>>>(priors, gt_boxes, gt_labels, out_loc, out_conf);
}